// round 4
// baseline (speedup 1.0000x reference)
#include <cuda_runtime.h>

#define DD 4096
#define LL 6
#define BLOCK 1024
// 1024 threads * float4 = 4096 = D; each thread owns 4 columns of every row.

__global__ __launch_bounds__(BLOCK, 1)
void crossnet_dcn_kernel(const float* __restrict__ x0g,
                         const float* __restrict__ wg,
                         const float* __restrict__ bg,
                         float* __restrict__ outg,
                         int B)
{
    __shared__ float s_part[32][13];   // preamble e-reduce scratch
    __shared__ float s_u[3][12];       // rotating atomic accumulators
    __shared__ float s_e[LL];          // e_l scalars

    const int tid  = threadIdx.x;
    const int lane = tid & 31;
    const int wid  = tid >> 5;

    const float4* w4 = reinterpret_cast<const float4*>(wg);
    const float4* b4 = reinterpret_cast<const float4*>(bg);
    const float4* x4 = reinterpret_cast<const float4*>(x0g);
    float4*       o4 = reinterpret_cast<float4*>(outg);

    // ---- w for this thread's 4 columns, all layers (24 regs) ----
    float4 wr[LL];
#pragma unroll
    for (int l = 0; l < LL; l++) wr[l] = w4[l * (DD / 4) + tid];

    // ---- preamble: d_L (vector, regs) and e_l = d_l . w_l (scalars) ----
    float4 dl = make_float4(0.f, 0.f, 0.f, 0.f);
    {
        float ep[LL];
#pragma unroll
        for (int l = 0; l < LL; l++) {
            ep[l] = dl.x * wr[l].x + dl.y * wr[l].y + dl.z * wr[l].z + dl.w * wr[l].w;
            float4 bv = b4[l * (DD / 4) + tid];
            dl.x += bv.x; dl.y += bv.y; dl.z += bv.z; dl.w += bv.w;
        }
#pragma unroll
        for (int o = 16; o > 0; o >>= 1)
#pragma unroll
            for (int l = 0; l < LL; l++) ep[l] += __shfl_xor_sync(0xffffffffu, ep[l], o);
        if (lane == 0)
#pragma unroll
            for (int l = 0; l < LL; l++) s_part[wid][l] = ep[l];
    }
    // zero all three accumulator buffers
    if (tid < 36) ((float*)s_u)[tid] = 0.f;
    __syncthreads();

    if (wid == 0) {
#pragma unroll
        for (int l = 0; l < LL; l++) {
            float t = s_part[lane][l];
#pragma unroll
            for (int o = 16; o > 0; o >>= 1) t += __shfl_xor_sync(0xffffffffu, t, o);
            if (lane == 0) s_e[l] = t;
        }
    }
    __syncthreads();

    // e into registers (stable after this point)
    float e[LL];
#pragma unroll
    for (int l = 0; l < LL; l++) e[l] = s_e[l];

    // ---- main loop: 2 rows per iteration, ONE barrier per iteration ----
    const int npairs = B >> 1;
    const int stride = gridDim.x;

    int pair = blockIdx.x;
    float4 pA = make_float4(0.f, 0.f, 0.f, 0.f);
    float4 pB = pA;
    if (pair < npairs) {
        pA = __ldcs(&x4[(size_t)(2 * pair)     * (DD / 4) + tid]);
        pB = __ldcs(&x4[(size_t)(2 * pair + 1) * (DD / 4) + tid]);
    }

    int cur = 0;   // accumulator buffer index, rotates mod 3
    for (; pair < npairs; pair += stride) {
        const float4 x0A = pA;
        const float4 x0B = pB;

        // zero next-next buffer (safe: its readers finished before the
        // previous barrier; its next atomics start after this barrier)
        int nxt = cur + 1; if (nxt == 3) nxt = 0;
        if (tid < 12) s_u[nxt][tid] = 0.f;

        // prefetch next pair (overlaps reduce + epilogue)
        int np = pair + stride;
        if (np < npairs) {
            pA = __ldcs(&x4[(size_t)(2 * np)     * (DD / 4) + tid]);
            pB = __ldcs(&x4[(size_t)(2 * np + 1) * (DD / 4) + tid]);
        }

        // per-thread partial dots: v[l] = rowA layer l, v[6+l] = rowB layer l
        float v[12];
#pragma unroll
        for (int l = 0; l < LL; l++) {
            float a = x0A.x * wr[l].x;
            a = fmaf(x0A.y, wr[l].y, a);
            a = fmaf(x0A.z, wr[l].z, a);
            a = fmaf(x0A.w, wr[l].w, a);
            v[l] = a;
            float c = x0B.x * wr[l].x;
            c = fmaf(x0B.y, wr[l].y, c);
            c = fmaf(x0B.z, wr[l].z, c);
            c = fmaf(x0B.w, wr[l].w, c);
            v[LL + l] = c;
        }

        // transposed multi-value warp reduce: rounds 16,8,4,2 then xor-1.
        // Value i ends on lanes {2i, 2i+1}.
        {
            bool hi = (lane & 16) != 0;
#pragma unroll
            for (int j = 0; j < 8; j++) {
                float vh   = (j + 8 < 12) ? v[j + 8] : 0.f;
                float send = hi ? v[j] : vh;
                float keep = hi ? vh : v[j];
                v[j] = keep + __shfl_xor_sync(0xffffffffu, send, 16);
            }
        }
#pragma unroll
        for (int r = 1; r < 4; r++) {
            const int dist = 16 >> r;
            const int nv   = 8 >> r;
            bool hi = (lane & dist) != 0;
#pragma unroll
            for (int j = 0; j < nv; j++) {
                float send = hi ? v[j] : v[j + nv];
                float keep = hi ? v[j + nv] : v[j];
                v[j] = keep + __shfl_xor_sync(0xffffffffu, send, dist);
            }
        }
        v[0] += __shfl_xor_sync(0xffffffffu, v[0], 1);

        // even lanes < 24 hold value idx = lane>>1: atomic-reduce across warps
        if ((lane & 1) == 0 && lane < 24)
            atomicAdd(&s_u[cur][lane >> 1], v[0]);

        __syncthreads();

        // every thread: read 12 reduced scalars, run recurrence redundantly
        float cA = 1.f, cB = 1.f;
#pragma unroll
        for (int l = 0; l < LL; l++) {
            float uA = s_u[cur][l];
            float uB = s_u[cur][LL + l];
            cA = fmaf(cA, uA, cA + e[l]);   // c = c*(1+u) + e
            cB = fmaf(cB, uB, cB + e[l]);
        }

        float4 rA, rB;
        rA.x = fmaf(x0A.x, cA, dl.x);
        rA.y = fmaf(x0A.y, cA, dl.y);
        rA.z = fmaf(x0A.z, cA, dl.z);
        rA.w = fmaf(x0A.w, cA, dl.w);
        rB.x = fmaf(x0B.x, cB, dl.x);
        rB.y = fmaf(x0B.y, cB, dl.y);
        rB.z = fmaf(x0B.z, cB, dl.z);
        rB.w = fmaf(x0B.w, cB, dl.w);

        __stcs(&o4[(size_t)(2 * pair)     * (DD / 4) + tid], rA);
        __stcs(&o4[(size_t)(2 * pair + 1) * (DD / 4) + tid], rB);

        cur = nxt;
    }
}

extern "C" void kernel_launch(void* const* d_in, const int* in_sizes, int n_in,
                              void* d_out, int out_size)
{
    const float* x0 = (const float*)d_in[0];   // inputs [B, D] f32
    const float* w  = (const float*)d_in[1];   // w [L, D, 1]  f32
    const float* b  = (const float*)d_in[2];   // b [L, D]     f32
    float* out      = (float*)d_out;           // [B, D]       f32

    const int B = in_sizes[0] / DD;

    static int sm_count = 0;
    if (sm_count == 0) {
        cudaDeviceGetAttribute(&sm_count, cudaDevAttrMultiProcessorCount, 0);
        if (sm_count <= 0) sm_count = 148;
    }

    crossnet_dcn_kernel<<<sm_count, BLOCK>>>(x0, w, b, out, B);
}